// round 14
// baseline (speedup 1.0000x reference)
#include <cuda_runtime.h>
#include <cuda_fp16.h>
#include <cstdint>

#define HID   512
#define SRC   2048
#define BATCH 64
#define NT    4096                       // total tiles: 4 nb x 16 st x 64 b
#define GRID  296                        // persistent CTAs (2 per SM)

// CTA tile M=128, N=128, K=512 in 8 KC=64 stages, depth-1 fused pipeline (R9 structure).
#define KC        64
#define A32_SLOT  32768                  // 128 rows x 64 fp32, 256B/row linear, 2 slots
#define B_SLOT    16384                  // 128 rows x 64 fp16, 128B/row XOR-swizzled, 2 slots
#define A16_SZ    16384                  // 128 rows x 64 fp16, XOR-swizzled, 1 slot
#define OFF_A32   0
#define OFF_B     (2 * A32_SLOT)         // 65536
#define OFF_A16   (OFF_B + 2 * B_SLOT)   // 98304
#define SMEM_BYTES (OFF_A16 + A16_SZ)    // 114688 -> 2 CTAs/SM

// ---------------- device scratch ----------------
__device__ __align__(16) __half g_W1h[HID * HID];
__device__ float g_cbias[BATCH * HID];
__device__ float g_part[4][BATCH][SRC];
__device__ int   g_tile_ctr;

// ---------------- helpers ----------------
__device__ __forceinline__ unsigned smem_u32(const void* p) {
    return (unsigned)__cvta_generic_to_shared(p);
}
__device__ __forceinline__ void ldsm4(uint32_t r[4], unsigned addr) {
    asm volatile("ldmatrix.sync.aligned.m8n8.x4.shared.b16 {%0,%1,%2,%3}, [%4];"
                 : "=r"(r[0]), "=r"(r[1]), "=r"(r[2]), "=r"(r[3]) : "r"(addr));
}
__device__ __forceinline__ void mma_fp16(float c[4], const uint32_t a[4], const uint32_t b[2]) {
    asm volatile(
        "mma.sync.aligned.m16n8k16.row.col.f32.f16.f16.f32 "
        "{%0,%1,%2,%3}, {%4,%5,%6,%7}, {%8,%9}, {%0,%1,%2,%3};"
        : "+f"(c[0]), "+f"(c[1]), "+f"(c[2]), "+f"(c[3])
        : "r"(a[0]), "r"(a[1]), "r"(a[2]), "r"(a[3]), "r"(b[0]), "r"(b[1]));
}
__device__ __forceinline__ void cp_async16(uint32_t dst, const void* src) {
    asm volatile("cp.async.cg.shared.global [%0], [%1], 16;" :: "r"(dst), "l"(src) : "memory");
}
__device__ __forceinline__ void cp_commit() {
    asm volatile("cp.async.commit_group;" ::: "memory");
}
__device__ __forceinline__ uint32_t packh2(float a, float b) {
    __half2 h = __floats2half2_rn(a, b);
    return *reinterpret_cast<uint32_t*>(&h);
}

// ---------------- kernel 1: W1 -> fp16 ----------------
__global__ void prep_w_kernel(const float* __restrict__ W1w) {
    int i = blockIdx.x * blockDim.x + threadIdx.x;
    if (i < HID * HID) g_W1h[i] = __float2half_rn(W1w[i]);
}

// ---------------- kernel 2: cbias (also resets the tile counter) ----------------
__global__ void cbias_kernel(const float* __restrict__ h,
                             const float* __restrict__ W2w,
                             const float* __restrict__ W2b,
                             const float* __restrict__ W1b) {
    __shared__ float hs[HID];
    const int b = blockIdx.x;
    const int o = blockIdx.y * 128 + threadIdx.x;
    if (b == 0 && blockIdx.y == 0 && threadIdx.x == 0) g_tile_ctr = GRID;
    for (int k = threadIdx.x; k < HID; k += 128) hs[k] = h[b * HID + k];
    __syncthreads();
    float acc = W2b[o] + W1b[o];
    const float* wr = W2w + o * HID;
#pragma unroll 8
    for (int k = 0; k < HID; k++) acc += hs[k] * wr[k];
    g_cbias[b * HID + o] = acc;
}

// ---------------- kernel 3: persistent fused cvt+GEMM+tanh+V-dot ----------------
// tile id t: nb = t&3 (fastest -> L2 sharing), st = (t>>2)&15, b = t>>6.
__global__ __launch_bounds__(256, 2) void attn_main_kernel(const float* __restrict__ enc,
                                                           const float* __restrict__ Vw) {
    extern __shared__ __align__(128) char smem[];
    const uint32_t sb = smem_u32(smem);
    __shared__ int sNextT;

    const int tid = threadIdx.x;
    const int lane = tid & 31;
    const int wid  = tid >> 5;
    const int warp_m = wid & 3;
    const int warp_n = wid >> 2;

    // issue loads for (tile, stage) into parity slot
    auto issue_load = [&](int t, int s, int slot) {
        const int nb = t & 3, st = (t >> 2) & 15, b = t >> 6;
        const float* encRow = enc + (size_t)(b * SRC + st * 128) * HID;
        const int o0 = nb * 128;
        const int kc = s * KC;
        const uint32_t a32 = sb + OFF_A32 + slot * A32_SLOT;
#pragma unroll
        for (int k = 0; k < 8; ++k) {
            const int q = tid + k * 256;          // 0..2047 16B units, linear
            const int row = q >> 4;
            const int u   = q & 15;
            cp_async16(a32 + q * 16, encRow + (size_t)row * HID + kc + u * 4);
        }
        const uint32_t bb = sb + OFF_B + slot * B_SLOT;
#pragma unroll
        for (int k = 0; k < 4; ++k) {
            const int p = tid + k * 256;          // 0..1023 16B units
            const int row = p >> 3;
            const int u   = p & 7;
            cp_async16(bb + row * 128 + ((u ^ (row & 7)) << 4),
                       g_W1h + (size_t)(o0 + row) * HID + kc + u * 8);
        }
        cp_commit();
    };

    auto convert_stage = [&](int slot) {
        const char* a32 = smem + OFF_A32 + slot * A32_SLOT;
        char* a16 = smem + OFF_A16;
#pragma unroll
        for (int k = 0; k < 8; ++k) {
            const int idx = tid + k * 256;        // float4 index 0..2047
            const float4 f = *reinterpret_cast<const float4*>(a32 + idx * 16);
            const int row = idx >> 4;
            const int u8  = idx & 15;
            const int u16 = u8 >> 1;
            uint2 v;
            v.x = packh2(f.x, f.y);
            v.y = packh2(f.z, f.w);
            *reinterpret_cast<uint2*>(a16 + row * 128 + ((u16 ^ (row & 7)) << 4)
                                      + (u8 & 1) * 8) = v;
        }
    };

    float acc[2][8][4];

    auto compute_stage = [&](int slot, int ks) {
        const uint32_t a16 = sb + OFF_A16;
        const uint32_t bb  = sb + OFF_B + slot * B_SLOT;
        uint32_t a[2][4];
#pragma unroll
        for (int mt = 0; mt < 2; mt++) {
            const int r = warp_m * 32 + mt * 16 + (lane & 15);
            const int u = (ks >> 3) + (lane >> 4);
            ldsm4(a[mt], a16 + r * 128 + ((u ^ (r & 7)) << 4));
        }
#pragma unroll
        for (int ntp = 0; ntp < 4; ntp++) {
            const int br = warp_n * 64 + ntp * 16 + ((lane >> 4) << 3) + (lane & 7);
            const int bu = (ks >> 3) + ((lane >> 3) & 1);
            uint32_t bh[4];
            ldsm4(bh, bb + br * 128 + ((bu ^ (br & 7)) << 4));
#pragma unroll
            for (int mt = 0; mt < 2; mt++) {
#pragma unroll
                for (int half = 0; half < 2; half++) {
                    mma_fp16(acc[mt][ntp * 2 + half], a[mt], bh + 2 * half);
                }
            }
        }
    };

    // ---- persistent loop ----
    int t = blockIdx.x;
    issue_load(t, 0, 0);

    while (t < NT) {
        const int nb = t & 3, st = (t >> 2) & 15, b = t >> 6;
        const int s0 = st * 128;
        const int o0 = nb * 128;

#pragma unroll
        for (int i = 0; i < 2; i++)
#pragma unroll
            for (int j = 0; j < 8; j++)
#pragma unroll
                for (int r = 0; r < 4; r++) acc[i][j][r] = 0.f;

#pragma unroll 1
        for (int s = 0; s < 8; ++s) {
            asm volatile("cp.async.wait_group 0;" ::: "memory");
            __syncthreads();                     // stage s (slot s&1) visible to all
            if (s == 0 && tid == 0) sNextT = atomicAdd(&g_tile_ctr, 1);
            const int pp = s & 1;
            if (s < 7) {
                issue_load(t, s + 1, pp ^ 1);
            } else {
                const int tn = sNextT;           // written at s==0; 7 barriers ago
                if (tn < NT) issue_load(tn, 0, pp ^ 1);
            }
            convert_stage(pp);
            __syncthreads();                     // A16 ready
#pragma unroll
            for (int ks = 0; ks < KC; ks += 16) compute_stage(pp, ks);
        }

        // ---- epilogue (next tile's stage-0 loads are in flight underneath) ----
        float rowsum[2][2];
        rowsum[0][0] = rowsum[0][1] = rowsum[1][0] = rowsum[1][1] = 0.f;
        const float* cbRow = g_cbias + b * HID;
#pragma unroll
        for (int nt = 0; nt < 8; nt++) {
            const int o = o0 + warp_n * 64 + nt * 8 + (lane & 3) * 2;
            const float cb0 = cbRow[o],     v0 = Vw[o];
            const float cb1 = cbRow[o + 1], v1 = Vw[o + 1];
#pragma unroll
            for (int mt = 0; mt < 2; mt++) {
                rowsum[mt][0] += tanhf(acc[mt][nt][0] + cb0) * v0;
                rowsum[mt][0] += tanhf(acc[mt][nt][1] + cb1) * v1;
                rowsum[mt][1] += tanhf(acc[mt][nt][2] + cb0) * v0;
                rowsum[mt][1] += tanhf(acc[mt][nt][3] + cb1) * v1;
            }
        }

        // sRed lives in the A16 region: NOT touched by the in-flight loads
        // (they target A32/B slot pp^1); compute readers are fenced below.
        float* sRed = reinterpret_cast<float*>(smem + OFF_A16);
        __syncthreads();                         // all warps done reading A16
#pragma unroll
        for (int mt = 0; mt < 2; mt++) {
#pragma unroll
            for (int j = 0; j < 2; j++) {
                float v = rowsum[mt][j];
                v += __shfl_xor_sync(0xffffffffu, v, 1);
                v += __shfl_xor_sync(0xffffffffu, v, 2);
                if ((lane & 3) == 0) {
                    const int row = warp_m * 32 + mt * 16 + (lane >> 2) + 8 * j;
                    sRed[row * 2 + warp_n] = v;
                }
            }
        }
        __syncthreads();
        if (tid < 128) {
            g_part[nb][b][s0 + tid] = sRed[tid * 2] + sRed[tid * 2 + 1];
        }
        __syncthreads();                         // sRed reads done before next convert
        t = sNextT;
    }
}

// ---------------- kernel 4: sum partials + softmax over S ----------------
__global__ void softmax_kernel(float* __restrict__ out) {
    __shared__ float sv[SRC];
    __shared__ float red[256];
    int b = blockIdx.x;
    int tid = threadIdx.x;

    float mx = -1e30f;
    for (int s = tid; s < SRC; s += 256) {
        float v = g_part[0][b][s] + g_part[1][b][s] + g_part[2][b][s] + g_part[3][b][s];
        sv[s] = v;
        mx = fmaxf(mx, v);
    }
    red[tid] = mx;
    __syncthreads();
    for (int st = 128; st > 0; st >>= 1) {
        if (tid < st) red[tid] = fmaxf(red[tid], red[tid + st]);
        __syncthreads();
    }
    mx = red[0];
    __syncthreads();

    float sum = 0.f;
    for (int s = tid; s < SRC; s += 256) {
        float e = expf(sv[s] - mx);
        sv[s] = e;
        sum += e;
    }
    red[tid] = sum;
    __syncthreads();
    for (int st = 128; st > 0; st >>= 1) {
        if (tid < st) red[tid] += red[tid + st];
        __syncthreads();
    }
    float inv = 1.0f / red[0];
    __syncthreads();

    for (int s = tid; s < SRC; s += 256) {
        out[(size_t)b * SRC + s] = sv[s] * inv;
    }
}

// ---------------- launch ----------------
extern "C" void kernel_launch(void* const* d_in, const int* in_sizes, int n_in,
                              void* d_out, int out_size) {
    const float* h    = (const float*)d_in[0];
    const float* enc  = (const float*)d_in[1];
    const float* W1w  = (const float*)d_in[2];
    const float* W1b  = (const float*)d_in[3];
    const float* W2w  = (const float*)d_in[4];
    const float* W2b  = (const float*)d_in[5];
    const float* Vw   = (const float*)d_in[6];
    float* out = (float*)d_out;

    cudaFuncSetAttribute(attn_main_kernel,
                         cudaFuncAttributeMaxDynamicSharedMemorySize, SMEM_BYTES);

    prep_w_kernel<<<(HID * HID + 511) / 512, 512>>>(W1w);
    cbias_kernel<<<dim3(BATCH, 4), 128>>>(h, W2w, W2b, W1b);
    attn_main_kernel<<<GRID, 256, SMEM_BYTES>>>(enc, Vw);
    softmax_kernel<<<BATCH, 256>>>(out);
}

// round 15
// speedup vs baseline: 1.6264x; 1.6264x over previous
#include <cuda_runtime.h>
#include <cuda_fp16.h>
#include <cstdint>

#define HID   512
#define SRC   2048
#define BATCH 64

// CTA tile M=128, N=128, K=512 in 16 KC=32 stages.
// A: LDG fp32 -> regs (1 stage ahead) -> cvt -> STS fp16 (2-slot A16 ring)
// B: cp.async fp16 (3-slot ring)
#define KC        32
#define A16_SLOT  10240                  // 128 rows x 32 fp16, 80B stride
#define B_SLOT    10240
#define OFF_A16   0                      // 2 slots: 20480
#define OFF_B     20480                  // 3 slots: 30720
#define SMEM_BYTES 51200

// ---------------- device scratch ----------------
__device__ __align__(16) __half g_W1h[HID * HID];
__device__ float g_cbias[BATCH * HID];
__device__ float g_part[4][BATCH][SRC];

// ---------------- helpers ----------------
__device__ __forceinline__ unsigned smem_u32(const void* p) {
    return (unsigned)__cvta_generic_to_shared(p);
}
__device__ __forceinline__ void ldsm4(uint32_t r[4], unsigned addr) {
    asm volatile("ldmatrix.sync.aligned.m8n8.x4.shared.b16 {%0,%1,%2,%3}, [%4];"
                 : "=r"(r[0]), "=r"(r[1]), "=r"(r[2]), "=r"(r[3]) : "r"(addr));
}
__device__ __forceinline__ void mma_fp16(float c[4], const uint32_t a[4], const uint32_t b[2]) {
    asm volatile(
        "mma.sync.aligned.m16n8k16.row.col.f32.f16.f16.f32 "
        "{%0,%1,%2,%3}, {%4,%5,%6,%7}, {%8,%9}, {%0,%1,%2,%3};"
        : "+f"(c[0]), "+f"(c[1]), "+f"(c[2]), "+f"(c[3])
        : "r"(a[0]), "r"(a[1]), "r"(a[2]), "r"(a[3]), "r"(b[0]), "r"(b[1]));
}
__device__ __forceinline__ void cp_async16(uint32_t dst, const void* src) {
    asm volatile("cp.async.cg.shared.global [%0], [%1], 16;" :: "r"(dst), "l"(src) : "memory");
}
__device__ __forceinline__ void cp_commit() {
    asm volatile("cp.async.commit_group;" ::: "memory");
}
__device__ __forceinline__ uint32_t packh2(float a, float b) {
    __half2 h = __floats2half2_rn(a, b);
    return *reinterpret_cast<uint32_t*>(&h);
}

// ---------------- kernel 1: W1 -> fp16 ----------------
__global__ void prep_w_kernel(const float* __restrict__ W1w) {
    int i = blockIdx.x * blockDim.x + threadIdx.x;
    if (i < HID * HID) g_W1h[i] = __float2half_rn(W1w[i]);
}

// ---------------- kernel 2: cbias ----------------
__global__ void cbias_kernel(const float* __restrict__ h,
                             const float* __restrict__ W2w,
                             const float* __restrict__ W2b,
                             const float* __restrict__ W1b) {
    __shared__ float hs[HID];
    const int b = blockIdx.x;
    const int o = blockIdx.y * 128 + threadIdx.x;
    for (int k = threadIdx.x; k < HID; k += 128) hs[k] = h[b * HID + k];
    __syncthreads();
    float acc = W2b[o] + W1b[o];
    const float* wr = W2w + o * HID;
#pragma unroll 8
    for (int k = 0; k < HID; k++) acc += hs[k] * wr[k];
    g_cbias[b * HID + o] = acc;
}

// ---------------- kernel 3: reg-staged A + cp.async B fp16 GEMM + tanh + V-dot ----------------
// grid (4 nb, 16 st, 64 b); 256 threads = 8 warps (4 M x 2 N).
__global__ __launch_bounds__(256, 2) void attn_main_kernel(const float* __restrict__ enc,
                                                           const float* __restrict__ Vw) {
    extern __shared__ __align__(128) char smem[];
    const uint32_t sb = smem_u32(smem);

    const int nb  = blockIdx.x;          // fastest -> 4 CTAs share enc rows via L2
    const int st  = blockIdx.y;
    const int b   = blockIdx.z;
    const int tid = threadIdx.x;
    const int lane = tid & 31;
    const int wid  = tid >> 5;
    const int warp_m = wid & 3;
    const int warp_n = wid >> 2;
    const int s0 = st * 128;
    const int o0 = nb * 128;

    const float* encRow = enc + (size_t)(b * SRC + s0) * HID;

    // per-thread A staging: 4 float4 units; q = tid + k*256 -> row q>>3, fp32 unit q&7
    const int arow0 = tid >> 3;          // rows arow0 + k*32
    const int au    = tid & 7;           // fp32 16B unit within row (cols au*4..au*4+3)
    float4 areg[4];

    auto ldg_stageA = [&](int s) {
        const float* p = encRow + (size_t)arow0 * HID + s * KC + au * 4;
#pragma unroll
        for (int k = 0; k < 4; ++k) {
            areg[k] = *reinterpret_cast<const float4*>(p + (size_t)k * 32 * HID);
        }
    };
    auto sts_stageA = [&](int s) {
        const uint32_t a16 = sb + OFF_A16 + (s & 1) * A16_SLOT;
#pragma unroll
        for (int k = 0; k < 4; ++k) {
            const int row = arow0 + k * 32;
            const uint32_t v0 = packh2(areg[k].x, areg[k].y);
            const uint32_t v1 = packh2(areg[k].z, areg[k].w);
            asm volatile("st.shared.v2.u32 [%0], {%1,%2};"
                         :: "r"(a16 + row * 80 + au * 8), "r"(v0), "r"(v1) : "memory");
        }
    };
    auto load_B = [&](int s) {
        const uint32_t bb = sb + OFF_B + (s % 3) * B_SLOT;
        const int kc = s * KC;
#pragma unroll
        for (int k = 0; k < 2; ++k) {
            const int p = tid + k * 256;          // 512 16B units
            const int row = p >> 2;
            const int u   = p & 3;
            cp_async16(bb + row * 80 + u * 16,
                       g_W1h + (size_t)(o0 + row) * HID + kc + u * 8);
        }
        cp_commit();
    };

    float acc[2][8][4];
#pragma unroll
    for (int i = 0; i < 2; i++)
#pragma unroll
        for (int j = 0; j < 8; j++)
#pragma unroll
            for (int r = 0; r < 4; r++) acc[i][j][r] = 0.f;

    // ---- prologue ----
    ldg_stageA(0);
    load_B(0);
    load_B(1);

    // ---- mainloop: 16 stages, one sync each ----
#pragma unroll 1
    for (int s = 0; s < 16; ++s) {
        if (s < 15) asm volatile("cp.async.wait_group 1;" ::: "memory");  // B(s) done
        else        asm volatile("cp.async.wait_group 0;" ::: "memory");
        sts_stageA(s);                    // regs -> A16[s&1]
        if (s < 15) ldg_stageA(s + 1);    // refill regs; lands during compute(s)
        __syncthreads();                  // A16(s) + B(s) visible; slot (s+2)%3 free
        if (s < 14) load_B(s + 2);

        const uint32_t a16 = sb + OFF_A16 + (s & 1) * A16_SLOT;
        const uint32_t bb  = sb + OFF_B + (s % 3) * B_SLOT;
#pragma unroll
        for (int ks = 0; ks < KC; ks += 16) {
            uint32_t a[2][4];
#pragma unroll
            for (int mt = 0; mt < 2; mt++) {
                const int r = warp_m * 32 + mt * 16 + (lane & 15);
                const int u = (ks >> 4) * 2 + (lane >> 4);
                ldsm4(a[mt], a16 + r * 80 + u * 16);
            }
#pragma unroll
            for (int ntp = 0; ntp < 4; ntp++) {
                const int br = warp_n * 64 + ntp * 16 + ((lane >> 4) << 3) + (lane & 7);
                const int bu = (ks >> 4) * 2 + ((lane >> 3) & 1);
                uint32_t bh[4];
                ldsm4(bh, bb + br * 80 + bu * 16);
#pragma unroll
                for (int mt = 0; mt < 2; mt++) {
#pragma unroll
                    for (int half = 0; half < 2; half++) {
                        mma_fp16(acc[mt][ntp * 2 + half], a[mt], bh + 2 * half);
                    }
                }
            }
        }
    }

    // ---- epilogue: tanh(acc + cbias) * V, reduce over 128 o-columns ----
    float rowsum[2][2];
    rowsum[0][0] = rowsum[0][1] = rowsum[1][0] = rowsum[1][1] = 0.f;

    const float* cbRow = g_cbias + b * HID;
#pragma unroll
    for (int nt = 0; nt < 8; nt++) {
        const int o = o0 + warp_n * 64 + nt * 8 + (lane & 3) * 2;
        const float cb0 = cbRow[o],     v0 = Vw[o];
        const float cb1 = cbRow[o + 1], v1 = Vw[o + 1];
#pragma unroll
        for (int mt = 0; mt < 2; mt++) {
            rowsum[mt][0] += tanhf(acc[mt][nt][0] + cb0) * v0;
            rowsum[mt][0] += tanhf(acc[mt][nt][1] + cb1) * v1;
            rowsum[mt][1] += tanhf(acc[mt][nt][2] + cb0) * v0;
            rowsum[mt][1] += tanhf(acc[mt][nt][3] + cb1) * v1;
        }
    }

    // sRed in A16 slot 0 region: compute(15) reads A16 slot 1 and B slot 0 only,
    // so these writes race with nothing; readers sync below.
    float* sRed = reinterpret_cast<float*>(smem);
    __syncthreads();                      // all warps done with compute(15) ldsm reads
#pragma unroll
    for (int mt = 0; mt < 2; mt++) {
#pragma unroll
        for (int j = 0; j < 2; j++) {
            float v = rowsum[mt][j];
            v += __shfl_xor_sync(0xffffffffu, v, 1);
            v += __shfl_xor_sync(0xffffffffu, v, 2);
            if ((lane & 3) == 0) {
                const int row = warp_m * 32 + mt * 16 + (lane >> 2) + 8 * j;
                sRed[row * 2 + warp_n] = v;
            }
        }
    }
    __syncthreads();

    if (tid < 128) {
        g_part[nb][b][s0 + tid] = sRed[tid * 2] + sRed[tid * 2 + 1];
    }
}

// ---------------- kernel 4: sum partials + softmax over S ----------------
__global__ void softmax_kernel(float* __restrict__ out) {
    __shared__ float sv[SRC];
    __shared__ float red[256];
    int b = blockIdx.x;
    int tid = threadIdx.x;

    float mx = -1e30f;
    for (int s = tid; s < SRC; s += 256) {
        float v = g_part[0][b][s] + g_part[1][b][s] + g_part[2][b][s] + g_part[3][b][s];
        sv[s] = v;
        mx = fmaxf(mx, v);
    }
    red[tid] = mx;
    __syncthreads();
    for (int st = 128; st > 0; st >>= 1) {
        if (tid < st) red[tid] = fmaxf(red[tid], red[tid + st]);
        __syncthreads();
    }
    mx = red[0];
    __syncthreads();

    float sum = 0.f;
    for (int s = tid; s < SRC; s += 256) {
        float e = expf(sv[s] - mx);
        sv[s] = e;
        sum += e;
    }
    red[tid] = sum;
    __syncthreads();
    for (int st = 128; st > 0; st >>= 1) {
        if (tid < st) red[tid] += red[tid + st];
        __syncthreads();
    }
    float inv = 1.0f / red[0];
    __syncthreads();

    for (int s = tid; s < SRC; s += 256) {
        out[(size_t)b * SRC + s] = sv[s] * inv;
    }
}

// ---------------- launch ----------------
extern "C" void kernel_launch(void* const* d_in, const int* in_sizes, int n_in,
                              void* d_out, int out_size) {
    const float* h    = (const float*)d_in[0];
    const float* enc  = (const float*)d_in[1];
    const float* W1w  = (const float*)d_in[2];
    const float* W1b  = (const float*)d_in[3];
    const float* W2w  = (const float*)d_in[4];
    const float* W2b  = (const float*)d_in[5];
    const float* Vw   = (const float*)d_in[6];
    float* out = (float*)d_out;

    cudaFuncSetAttribute(attn_main_kernel,
                         cudaFuncAttributeMaxDynamicSharedMemorySize, SMEM_BYTES);

    prep_w_kernel<<<(HID * HID + 511) / 512, 512>>>(W1w);
    cbias_kernel<<<dim3(BATCH, 4), 128>>>(h, W2w, W2b, W1b);
    attn_main_kernel<<<dim3(4, SRC / 128, BATCH), 256, SMEM_BYTES>>>(enc, Vw);
    softmax_kernel<<<BATCH, 256>>>(out);
}